// round 4
// baseline (speedup 1.0000x reference)
#include <cuda_runtime.h>
#include <cuda_bf16.h>
#include <math.h>
#include <stdint.h>

// Problem constants (fixed for this dataset)
#define NNODES 50000
#define MAXE   262144
#define DDIM   128
#define HDIM   256
#define NEXP   4

// ---------------- device scratch (static allocation only) ----------------
__device__ int   g_counts[NEXP];
__device__ int   g_flag64;
__device__ int   g_bucket[NEXP][MAXE];      // 4 MB
__device__ float g_topv[MAXE];              // 1 MB
__device__ float g_partial[4096][NEXP];     // per gate-block prob sums
// pre-permuted, tf32-rounded W1 for all 4 experts:
// cat [0,65536) K=256 | dist [65536,98304) | mul [98304,131072) | all [131072,262144)
__device__ float g_w1p[262144];

#define OFF_CAT  0
#define OFF_DIST 65536
#define OFF_MUL  98304
#define OFF_ALL  131072

// ---------------- helpers ----------------
__device__ __forceinline__ uint32_t f2tf32(float x) {
    uint32_t r;
    asm("cvt.rna.tf32.f32 %0, %1;" : "=r"(r) : "f"(x));
    return r;
}

__device__ __forceinline__ void split_tf32(float x, float& hi, float& lo) {
    uint32_t h = f2tf32(x);
    hi = __uint_as_float(h);
    lo = __uint_as_float(f2tf32(x - hi));
}

__device__ __forceinline__ void mma_tf32(float c[4],
                                         uint32_t a0, uint32_t a1, uint32_t a2, uint32_t a3,
                                         uint32_t b0, uint32_t b1) {
    asm volatile(
        "mma.sync.aligned.m16n8k8.row.col.f32.tf32.tf32.f32 "
        "{%0,%1,%2,%3}, {%4,%5,%6,%7}, {%8,%9}, {%0,%1,%2,%3};"
        : "+f"(c[0]), "+f"(c[1]), "+f"(c[2]), "+f"(c[3])
        : "r"(a0), "r"(a1), "r"(a2), "r"(a3), "r"(b0), "r"(b1));
}

__device__ __forceinline__ void cp_async16(uint32_t smem_addr, const void* gptr) {
    asm volatile("cp.async.cg.shared.global [%0], [%1], 16;\n"
                 :: "r"(smem_addr), "l"(gptr));
}
__device__ __forceinline__ void cp_async_commit() {
    asm volatile("cp.async.commit_group;\n");
}
__device__ __forceinline__ void cp_async_wait0() {
    asm volatile("cp.async.wait_group 0;\n");
}

// ---------------- kernel 0: init + index dtype sniff ----------------
__global__ void k_init(const void* uptr) {
    if (threadIdx.x < NEXP) g_counts[threadIdx.x] = 0;
    if (threadIdx.x == 0) {
        const int* p = (const int*)uptr;
        int is64 = 1;
        #pragma unroll 1
        for (int i = 0; i < 64; i++) {
            if (p[2 * i + 1] != 0) { is64 = 0; break; }
        }
        g_flag64 = is64;
    }
}

// ---------------- kernel 0b: pre-permute + tf32-round W1 ----------------
// Output col layout per 32-col segment: newcol = seg*32 + (c&7)*4 + ((c>>3)&3)
__global__ __launch_bounds__(256) void k_prep(
    const float* __restrict__ w_cat, const float* __restrict__ w_dist,
    const float* __restrict__ w_mul, const float* __restrict__ w_all)
{
    const int idx = blockIdx.x * 256 + threadIdx.x;   // [0, 262144)
    const float* src;
    int base;
    if (idx < OFF_DIST)      { src = w_cat;  base = OFF_CAT;  }
    else if (idx < OFF_MUL)  { src = w_dist; base = OFF_DIST; }
    else if (idx < OFF_ALL)  { src = w_mul;  base = OFF_MUL;  }
    else                     { src = w_all;  base = OFF_ALL;  }
    const int r = idx - base;
    const int c = r & 255;
    const int pc = (c & 0xE0) | ((c & 7) << 2) | ((c >> 3) & 3);
    g_w1p[base + (r & ~255) + pc] = __uint_as_float(f2tf32(src[r]));
}

// ---------------- kernel 1: gate (softmax + top-1 + bucketing) ----------------
__global__ __launch_bounds__(256) void k_gate(
    const float* __restrict__ z,
    const void*  __restrict__ u_, const void* __restrict__ v_,
    const float* __restrict__ gate_w,   // [512,4] row-major
    const float* __restrict__ gate_b,   // [4]
    int E)
{
    __shared__ __align__(16) float sgw[512 * 4];
    __shared__ float wpart[8][NEXP];
    __shared__ int   sarg[64];
    __shared__ int   srank[64];
    __shared__ int   scnt[NEXP];
    __shared__ int   sbase[NEXP];

    const int tid  = threadIdx.x;
    const int warp = tid >> 5;
    const int lane = tid & 31;

    for (int t = tid; t < 2048; t += 256) sgw[t] = gate_w[t];
    if (tid < NEXP) scnt[tid] = 0;
    __syncthreads();

    const int flag64 = g_flag64;
    const float4* gw4 = reinterpret_cast<const float4*>(sgw);

    float p0 = 0.f, p1 = 0.f, p2 = 0.f, p3 = 0.f;

    #pragma unroll 1
    for (int t = 0; t < 8; t++) {
        const int e = (int)blockIdx.x * 64 + warp * 8 + t;
        if (e >= E) break;

        int uu, vv;
        if (flag64) {
            uu = (int)((const long long*)u_)[e];
            vv = (int)((const long long*)v_)[e];
        } else {
            uu = ((const int*)u_)[e];
            vv = ((const int*)v_)[e];
        }
        const float* zu = z + (size_t)uu * DDIM;
        const float* zv = z + (size_t)vv * DDIM;

        float g0 = 0.f, g1 = 0.f, g2 = 0.f, g3 = 0.f;
        #pragma unroll
        for (int kk = 0; kk < 4; kk++) {
            const int k = lane + kk * 32;
            const float a = zu[k];
            const float b = zv[k];
            const float d = fabsf(a - b);
            const float m = a * b;
            const float4 wA = gw4[k];
            const float4 wB = gw4[128 + k];
            const float4 wD = gw4[256 + k];
            const float4 wM = gw4[384 + k];
            g0 += a * wA.x + b * wB.x + d * wD.x + m * wM.x;
            g1 += a * wA.y + b * wB.y + d * wD.y + m * wM.y;
            g2 += a * wA.z + b * wB.z + d * wD.z + m * wM.z;
            g3 += a * wA.w + b * wB.w + d * wD.w + m * wM.w;
        }
        #pragma unroll
        for (int off = 16; off; off >>= 1) {
            g0 += __shfl_xor_sync(0xffffffffu, g0, off);
            g1 += __shfl_xor_sync(0xffffffffu, g1, off);
            g2 += __shfl_xor_sync(0xffffffffu, g2, off);
            g3 += __shfl_xor_sync(0xffffffffu, g3, off);
        }

        if (lane == 0) {
            float l[NEXP];
            l[0] = g0 + gate_b[0]; l[1] = g1 + gate_b[1];
            l[2] = g2 + gate_b[2]; l[3] = g3 + gate_b[3];
            float mx = l[0];
            #pragma unroll
            for (int j = 1; j < NEXP; j++) mx = fmaxf(mx, l[j]);
            float ex[NEXP]; float s = 0.f;
            #pragma unroll
            for (int j = 0; j < NEXP; j++) { ex[j] = expf(l[j] - mx); s += ex[j]; }
            const float inv = 1.f / s;
            float pr[NEXP];
            #pragma unroll
            for (int j = 0; j < NEXP; j++) pr[j] = ex[j] * inv;
            int arg = 0; float best = pr[0];
            #pragma unroll
            for (int j = 1; j < NEXP; j++) if (pr[j] > best) { best = pr[j]; arg = j; }

            g_topv[e] = best;
            sarg[warp * 8 + t] = arg;

            p0 += pr[0]; p1 += pr[1]; p2 += pr[2]; p3 += pr[3];
        }
    }

    if (lane == 0) {
        wpart[warp][0] = p0; wpart[warp][1] = p1;
        wpart[warp][2] = p2; wpart[warp][3] = p3;
    }
    __syncthreads();

    // block-local ranks -> 4 global atomics per block
    const int e0 = (int)blockIdx.x * 64 + tid;
    if (tid < 64 && e0 < E) {
        srank[tid] = atomicAdd(&scnt[sarg[tid]], 1);
    }
    __syncthreads();
    if (tid < NEXP) {
        sbase[tid] = atomicAdd(&g_counts[tid], scnt[tid]);
        float s = 0.f;
        #pragma unroll
        for (int w = 0; w < 8; w++) s += wpart[w][tid];
        g_partial[blockIdx.x][tid] = s;
    }
    __syncthreads();
    if (tid < 64 && e0 < E) {
        const int a = sarg[tid];
        g_bucket[a][sbase[a] + srank[tid]] = e0;
    }
}

// ---------------- kernels 2-5: fused expert MLPs (tf32x2, vectorized frags) --
// MODE: 0 = cat K=256; 1 = dist K=128; 2 = mul K=128; 3 = all K=512
// X stored with edge-perm pe(e)=(e&7)*8+(e>>3)  -> A frags via LDS.128
// W pre-permuted+tf32-rounded in g_w1p          -> B frags via LDS.128, no cvt

#define KC      16
#define XSTR    72
#define WSTR    264
#define BUFSZ   (2 * KC * XSTR + KC * WSTR)   // 6528 floats

template <int K, int MODE>
__global__ __launch_bounds__(256, 2) void k_expert(
    const float* __restrict__ z,
    const void*  __restrict__ u_, const void* __restrict__ v_,
    int w1off,                     // offset into g_w1p
    const float* __restrict__ b1,  // [256]
    const float* __restrict__ w2,  // [256,1]
    const float* __restrict__ b2,  // [1]
    float* __restrict__ out,
    int expert)
{
    extern __shared__ __align__(16) float sm[];
    float* sb1 = sm + 2 * BUFSZ;        // [256]
    float* sw2 = sb1 + 256;             // [256]
    float* red = sw2 + 256;             // [64][8]
    float* stv = red + 512;             // [64]
    int*   se  = (int*)(stv + 64);      // [64]
    int*   su  = se + 64;               // [64]
    int*   sv  = su + 64;               // [64]

    const float* w1 = g_w1p + w1off;

    const int tid  = threadIdx.x;
    const int warp = tid >> 5;
    const int lane = tid & 31;
    const int lq   = lane & 3;
    const int lg   = lane >> 2;

    if (tid < HDIM) { sb1[tid] = b1[tid]; sw2[tid] = w2[tid]; }
    const float b2s    = b2[0];
    const int   flag64 = g_flag64;
    const int   count  = g_counts[expert];
    const int   ntiles = (count + 63) >> 6;
    constexpr int NCH  = K / KC;

    // W cp.async mapping: 4 x 16B per thread per chunk (cols already permuted)
    int wr[4], wc[4];
    #pragma unroll
    for (int i = 0; i < 4; i++) {
        const int idx = tid + i * 256;
        wr[i] = idx >> 6;
        wc[i] = (idx & 63) << 2;
    }
    // X mapping: edge xe, dims xj..xj+3 ; store col = pe(xe)
    const int xe  = tid >> 2;
    const int xpe = (xe & 7) * 8 + (xe >> 3);
    const int xj  = (tid & 3) << 2;

    for (int tile = blockIdx.x; tile < ntiles; tile += gridDim.x) {
        __syncthreads();   // guard smem reuse across tiles
        const int base = tile * 64;
        const int nE   = min(64, count - base);

        if (tid < 64) {
            int e = (tid < nE) ? g_bucket[expert][base + tid] : -1;
            se[tid]  = e;
            stv[tid] = (e >= 0) ? g_topv[e] : 0.f;
            int uu = 0, vv = 0;
            if (e >= 0) {
                if (flag64) {
                    uu = (int)((const long long*)u_)[e];
                    vv = (int)((const long long*)v_)[e];
                } else {
                    uu = ((const int*)u_)[e];
                    vv = ((const int*)v_)[e];
                }
            }
            su[tid] = uu; sv[tid] = vv;
        }
        __syncthreads();

        const float* zu = z + (size_t)su[xe] * DDIM;
        const float* zv = z + (size_t)sv[xe] * DDIM;

        float acc[4][4][4];
        #pragma unroll
        for (int m = 0; m < 4; m++)
            #pragma unroll
            for (int n = 0; n < 4; n++)
                #pragma unroll
                for (int q = 0; q < 4; q++) acc[m][n][q] = 0.f;

        // ---- prologue: chunk 0 into buffer 0 ----
        {
            float* bW = sm + 2 * KC * XSTR;
            #pragma unroll
            for (int i = 0; i < 4; i++) {
                const uint32_t dst = (uint32_t)__cvta_generic_to_shared(bW + wr[i] * WSTR + wc[i]);
                cp_async16(dst, w1 + (size_t)wr[i] * HDIM + wc[i]);
            }
            cp_async_commit();
            const float4 xa = *reinterpret_cast<const float4*>(zu + xj);
            const float4 xb = *reinterpret_cast<const float4*>(zv + xj);
            const float av[4] = { xa.x, xa.y, xa.z, xa.w };
            const float bv[4] = { xb.x, xb.y, xb.z, xb.w };
            #pragma unroll
            for (int i = 0; i < 4; i++) {
                float val;
                if (MODE == 0)      val = av[i];
                else if (MODE == 1) val = fabsf(av[i] - bv[i]);
                else if (MODE == 2) val = av[i] * bv[i];
                else                val = av[i];
                float hi, lo;
                split_tf32(val, hi, lo);
                sm[(xj + i) * XSTR + xpe]             = hi;
                sm[KC * XSTR + (xj + i) * XSTR + xpe] = lo;
            }
            cp_async_wait0();
        }
        __syncthreads();

        #pragma unroll 1
        for (int cb = 0; cb < NCH; cb++) {
            float* cur = sm + (cb & 1) * BUFSZ;
            float* nxt = sm + ((cb + 1) & 1) * BUFSZ;

            // ---- issue next-chunk loads (overlap with compute below) ----
            float4 xa, xb;
            const bool more = (cb + 1 < NCH);
            if (more) {
                const int kb2 = (cb + 1) * KC;
                float* bW = nxt + 2 * KC * XSTR;
                #pragma unroll
                for (int i = 0; i < 4; i++) {
                    const uint32_t dst = (uint32_t)__cvta_generic_to_shared(bW + wr[i] * WSTR + wc[i]);
                    cp_async16(dst, w1 + (size_t)(kb2 + wr[i]) * HDIM + wc[i]);
                }
                cp_async_commit();
                const int d0 = kb2 & 127;
                xa = *reinterpret_cast<const float4*>(zu + d0 + xj);
                xb = *reinterpret_cast<const float4*>(zv + d0 + xj);
            }

            // ---- tensor compute on current buffer ----
            const float* cXhi = cur;
            const float* cXlo = cur + KC * XSTR;
            const float* cW   = cur + 2 * KC * XSTR;

            #pragma unroll
            for (int k8 = 0; k8 < 2; k8++) {
                const int kr = k8 * 8 + lq;

                // B fragments: 2 x LDS.128, already tf32
                const float4 wk0 = *reinterpret_cast<const float4*>(
                    &cW[kr * WSTR + warp * 32 + lg * 4]);
                const float4 wk4 = *reinterpret_cast<const float4*>(
                    &cW[(kr + 4) * WSTR + warp * 32 + lg * 4]);
                const uint32_t b0[4] = { __float_as_uint(wk0.x), __float_as_uint(wk0.y),
                                         __float_as_uint(wk0.z), __float_as_uint(wk0.w) };
                const uint32_t b1r[4] = { __float_as_uint(wk4.x), __float_as_uint(wk4.y),
                                          __float_as_uint(wk4.z), __float_as_uint(wk4.w) };

                // A fragments: 8 x LDS.128 (hi+lo, k and k+4, two 4-edge groups)
                const float4 hk0a = *reinterpret_cast<const float4*>(&cXhi[kr * XSTR + lg * 8]);
                const float4 hk0b = *reinterpret_cast<const float4*>(&cXhi[kr * XSTR + lg * 8 + 4]);
                const float4 hk4a = *reinterpret_cast<const float4*>(&cXhi[(kr + 4) * XSTR + lg * 8]);
                const float4 hk4b = *reinterpret_cast<const float4*>(&cXhi[(kr + 4) * XSTR + lg * 8 + 4]);
                const float4 lk0a = *reinterpret_cast<const float4*>(&cXlo[kr * XSTR + lg * 8]);
                const float4 lk0b = *reinterpret_cast<const float4*>(&cXlo[kr * XSTR + lg * 8 + 4]);
                const float4 lk4a = *reinterpret_cast<const float4*>(&cXlo[(kr + 4) * XSTR + lg * 8]);
                const float4 lk4b = *reinterpret_cast<const float4*>(&cXlo[(kr + 4) * XSTR + lg * 8 + 4]);

                const uint32_t ah[4][4] = {
                    { __float_as_uint(hk0a.x), __float_as_uint(hk0a.y),
                      __float_as_uint(hk4a.x), __float_as_uint(hk4a.y) },
                    { __float_as_uint(hk0a.z), __float_as_uint(hk0a.w),
                      __float_as_uint(hk4a.z), __float_as_uint(hk4a.w) },
                    { __float_as_uint(hk0b.x), __float_as_uint(hk0b.y),
                      __float_as_uint(hk4b.x), __float_as_uint(hk4b.y) },
                    { __float_as_uint(hk0b.z), __float_as_uint(hk0b.w),
                      __float_as_uint(hk4b.z), __float_as_uint(hk4b.w) } };
                const uint32_t al[4][4] = {
                    { __float_as_uint(lk0a.x), __float_as_uint(lk0a.y),
                      __float_as_uint(lk4a.x), __float_as_uint(lk4a.y) },
                    { __float_as_uint(lk0a.z), __float_as_uint(lk0a.w),
                      __float_as_uint(lk4a.z), __float_as_uint(lk4a.w) },
                    { __float_as_uint(lk0b.x), __float_as_uint(lk0b.y),
                      __float_as_uint(lk4b.x), __float_as_uint(lk4b.y) },
                    { __float_as_uint(lk0b.z), __float_as_uint(lk0b.w),
                      __float_as_uint(lk4b.z), __float_as_uint(lk4b.w) } };

                #pragma unroll
                for (int m = 0; m < 4; m++) {
                    #pragma unroll
                    for (int n = 0; n < 4; n++) {
                        mma_tf32(acc[m][n], al[m][0], al[m][1], al[m][2], al[m][3], b0[n], b1r[n]);
                        mma_tf32(acc[m][n], ah[m][0], ah[m][1], ah[m][2], ah[m][3], b0[n], b1r[n]);
                    }
                }
            }

            // ---- store next-chunk X into alternate buffer ----
            if (more) {
                const int type = ((cb + 1) * KC) >> 7;
                const float av[4] = { xa.x, xa.y, xa.z, xa.w };
                const float bv[4] = { xb.x, xb.y, xb.z, xb.w };
                #pragma unroll
                for (int i = 0; i < 4; i++) {
                    float val;
                    if (MODE == 0)      val = (type == 0) ? av[i] : bv[i];
                    else if (MODE == 1) val = fabsf(av[i] - bv[i]);
                    else if (MODE == 2) val = av[i] * bv[i];
                    else {
                        if (type == 0)      val = av[i];
                        else if (type == 1) val = bv[i];
                        else if (type == 2) val = fabsf(av[i] - bv[i]);
                        else                val = av[i] * bv[i];
                    }
                    float hi, lo;
                    split_tf32(val, hi, lo);
                    nxt[(xj + i) * XSTR + xpe]             = hi;
                    nxt[KC * XSTR + (xj + i) * XSTR + xpe] = lo;
                }
            }
            cp_async_wait0();
            __syncthreads();
        }

        // ---- epilogue: relu + layer-2 dot, reduce ----
        float ep[4][2];
        #pragma unroll
        for (int m = 0; m < 4; m++) { ep[m][0] = 0.f; ep[m][1] = 0.f; }

        #pragma unroll
        for (int n = 0; n < 4; n++) {
            const int c0 = warp * 32 + n * 8 + 2 * lq;
            const float bb0 = sb1[c0],     bb1 = sb1[c0 + 1];
            const float ww0 = sw2[c0],     ww1 = sw2[c0 + 1];
            #pragma unroll
            for (int m = 0; m < 4; m++) {
                ep[m][0] += fmaxf(acc[m][n][0] + bb0, 0.f) * ww0
                          + fmaxf(acc[m][n][1] + bb1, 0.f) * ww1;
                ep[m][1] += fmaxf(acc[m][n][2] + bb0, 0.f) * ww0
                          + fmaxf(acc[m][n][3] + bb1, 0.f) * ww1;
            }
        }
        #pragma unroll
        for (int m = 0; m < 4; m++) {
            #pragma unroll
            for (int off = 1; off <= 2; off <<= 1) {
                ep[m][0] += __shfl_xor_sync(0xffffffffu, ep[m][0], off);
                ep[m][1] += __shfl_xor_sync(0xffffffffu, ep[m][1], off);
            }
        }
        if (lq == 0) {
            #pragma unroll
            for (int m = 0; m < 4; m++) {
                red[(m * 16 + lg) * 8 + warp]       = ep[m][0];
                red[(m * 16 + lg + 8) * 8 + warp]   = ep[m][1];
            }
        }
        __syncthreads();

        if (tid < 64 && se[tid] >= 0) {
            float s = 0.f;
            #pragma unroll
            for (int w = 0; w < 8; w++) s += red[tid * 8 + w];
            out[se[tid]] = stv[tid] * (s + b2s);
        }
    }
}

// ---------------- kernel 6: aux loss reduction (deterministic) ----------------
__global__ __launch_bounds__(256) void k_aux(float* out, int out_size, int nblocks, int E)
{
    __shared__ float s[256];
    float acc[NEXP] = {0.f, 0.f, 0.f, 0.f};
    for (int i = threadIdx.x; i < nblocks; i += 256) {
        #pragma unroll
        for (int j = 0; j < NEXP; j++) acc[j] += g_partial[i][j];
    }
    float tot[NEXP];
    #pragma unroll
    for (int j = 0; j < NEXP; j++) {
        s[threadIdx.x] = acc[j];
        __syncthreads();
        for (int st = 128; st; st >>= 1) {
            if (threadIdx.x < st) s[threadIdx.x] += s[threadIdx.x + st];
            __syncthreads();
        }
        tot[j] = s[0];
        __syncthreads();
    }
    if (threadIdx.x == 0 && out_size > E) {
        float aux = 0.f;
        const float invE = 1.f / (float)E;
        #pragma unroll
        for (int j = 0; j < NEXP; j++) {
            const float m = tot[j] * invE;
            aux += m * m;
        }
        out[E] = aux * (float)NEXP;
    }
}

// ---------------- host launcher ----------------
#define EXP_SMEM ((2 * BUFSZ + 256 + 256 + 512 + 64 + 192) * 4)

extern "C" void kernel_launch(void* const* d_in, const int* in_sizes, int n_in,
                              void* d_out, int out_size)
{
    const float* z       = (const float*)d_in[0];
    const void*  u       = d_in[1];
    const void*  v       = d_in[2];
    const float* gate_w  = (const float*)d_in[3];
    const float* gate_b  = (const float*)d_in[4];
    const float* cat_w1  = (const float*)d_in[5];
    const float* cat_b1  = (const float*)d_in[6];
    const float* cat_w2  = (const float*)d_in[7];
    const float* cat_b2  = (const float*)d_in[8];
    const float* dist_w1 = (const float*)d_in[9];
    const float* dist_b1 = (const float*)d_in[10];
    const float* dist_w2 = (const float*)d_in[11];
    const float* dist_b2 = (const float*)d_in[12];
    const float* mul_w1  = (const float*)d_in[13];
    const float* mul_b1  = (const float*)d_in[14];
    const float* mul_w2  = (const float*)d_in[15];
    const float* mul_b2  = (const float*)d_in[16];
    const float* all_w1  = (const float*)d_in[17];
    const float* all_b1  = (const float*)d_in[18];
    const float* all_w2  = (const float*)d_in[19];
    const float* all_b2  = (const float*)d_in[20];
    float* out = (float*)d_out;

    const int E = in_sizes[1];                 // 262144
    const int gateBlocks = (E + 63) / 64;      // 4096

    cudaFuncSetAttribute(k_expert<256, 0>, cudaFuncAttributeMaxDynamicSharedMemorySize, EXP_SMEM);
    cudaFuncSetAttribute(k_expert<128, 1>, cudaFuncAttributeMaxDynamicSharedMemorySize, EXP_SMEM);
    cudaFuncSetAttribute(k_expert<128, 2>, cudaFuncAttributeMaxDynamicSharedMemorySize, EXP_SMEM);
    cudaFuncSetAttribute(k_expert<512, 3>, cudaFuncAttributeMaxDynamicSharedMemorySize, EXP_SMEM);

    k_init<<<1, 256>>>(u);
    k_prep<<<1024, 256>>>(cat_w1, dist_w1, mul_w1, all_w1);
    k_gate<<<gateBlocks, 256>>>(z, u, v, gate_w, gate_b, E);

    k_expert<256, 0><<<1024, 256, EXP_SMEM>>>(z, u, v, OFF_CAT,  cat_b1,  cat_w2,  cat_b2,  out, 0);
    k_expert<128, 1><<<1024, 256, EXP_SMEM>>>(z, u, v, OFF_DIST, dist_b1, dist_w2, dist_b2, out, 1);
    k_expert<128, 2><<<1024, 256, EXP_SMEM>>>(z, u, v, OFF_MUL,  mul_b1,  mul_w2,  mul_b2,  out, 2);
    k_expert<512, 3><<<1024, 256, EXP_SMEM>>>(z, u, v, OFF_ALL,  all_b1,  all_w2,  all_b2,  out, 3);

    k_aux<<<1, 256>>>(out, out_size, gateBlocks, E);
}

// round 5
// speedup vs baseline: 1.3862x; 1.3862x over previous
#include <cuda_runtime.h>
#include <cuda_bf16.h>
#include <math.h>
#include <stdint.h>

// Problem constants (fixed for this dataset)
#define NNODES 50000
#define MAXE   262144
#define DDIM   128
#define HDIM   256
#define NEXP   4

// ---------------- device scratch (static allocation only) ----------------
__device__ int   g_counts[NEXP];
__device__ int   g_flag64;
__device__ int   g_bucket[NEXP][MAXE];      // 4 MB
__device__ float g_topv[MAXE];              // 1 MB
__device__ float g_partial[4096][NEXP];     // per gate-block prob sums
// tf32-pre-rounded W1 for all 4 experts (row-major [K,256] each)
__device__ float g_w1p[262144];

#define OFF_CAT  0
#define OFF_DIST 65536
#define OFF_MUL  98304
#define OFF_ALL  131072

// ---------------- helpers ----------------
__device__ __forceinline__ uint32_t f2tf32(float x) {
    uint32_t r;
    asm("cvt.rna.tf32.f32 %0, %1;" : "=r"(r) : "f"(x));
    return r;
}

__device__ __forceinline__ void mma_tf32(float c[4],
                                         uint32_t a0, uint32_t a1, uint32_t a2, uint32_t a3,
                                         uint32_t b0, uint32_t b1) {
    asm volatile(
        "mma.sync.aligned.m16n8k8.row.col.f32.tf32.tf32.f32 "
        "{%0,%1,%2,%3}, {%4,%5,%6,%7}, {%8,%9}, {%0,%1,%2,%3};"
        : "+f"(c[0]), "+f"(c[1]), "+f"(c[2]), "+f"(c[3])
        : "r"(a0), "r"(a1), "r"(a2), "r"(a3), "r"(b0), "r"(b1));
}

__device__ __forceinline__ void cp_async16(uint32_t smem_addr, const void* gptr) {
    asm volatile("cp.async.cg.shared.global [%0], [%1], 16;\n"
                 :: "r"(smem_addr), "l"(gptr));
}
__device__ __forceinline__ void cp_async_commit() {
    asm volatile("cp.async.commit_group;\n");
}
__device__ __forceinline__ void cp_async_wait0() {
    asm volatile("cp.async.wait_group 0;\n");
}

// ---------------- kernel 0: init + index dtype sniff ----------------
__global__ void k_init(const void* uptr) {
    if (threadIdx.x < NEXP) g_counts[threadIdx.x] = 0;
    if (threadIdx.x == 0) {
        const int* p = (const int*)uptr;
        int is64 = 1;
        #pragma unroll 1
        for (int i = 0; i < 64; i++) {
            if (p[2 * i + 1] != 0) { is64 = 0; break; }
        }
        g_flag64 = is64;
    }
}

// ---------------- kernel 0b: tf32-round W1 (no permutation) ----------------
__global__ __launch_bounds__(256) void k_prep(
    const float* __restrict__ w_cat, const float* __restrict__ w_dist,
    const float* __restrict__ w_mul, const float* __restrict__ w_all)
{
    const int idx = blockIdx.x * 256 + threadIdx.x;   // [0, 262144)
    const float* src;
    int base;
    if (idx < OFF_DIST)      { src = w_cat;  base = OFF_CAT;  }
    else if (idx < OFF_MUL)  { src = w_dist; base = OFF_DIST; }
    else if (idx < OFF_ALL)  { src = w_mul;  base = OFF_MUL;  }
    else                     { src = w_all;  base = OFF_ALL;  }
    const int r = idx - base;
    g_w1p[idx] = __uint_as_float(f2tf32(src[r]));
}

// ---------------- kernel 1: gate (softmax + top-1 + bucketing) ----------------
__global__ __launch_bounds__(256) void k_gate(
    const float* __restrict__ z,
    const void*  __restrict__ u_, const void* __restrict__ v_,
    const float* __restrict__ gate_w,   // [512,4] row-major
    const float* __restrict__ gate_b,   // [4]
    int E)
{
    __shared__ __align__(16) float sgw[512 * 4];
    __shared__ float wpart[8][NEXP];
    __shared__ int   sarg[64];
    __shared__ int   srank[64];
    __shared__ int   scnt[NEXP];
    __shared__ int   sbase[NEXP];

    const int tid  = threadIdx.x;
    const int warp = tid >> 5;
    const int lane = tid & 31;

    for (int t = tid; t < 2048; t += 256) sgw[t] = gate_w[t];
    if (tid < NEXP) scnt[tid] = 0;
    __syncthreads();

    const int flag64 = g_flag64;
    const float4* gw4 = reinterpret_cast<const float4*>(sgw);

    float p0 = 0.f, p1 = 0.f, p2 = 0.f, p3 = 0.f;

    #pragma unroll 1
    for (int t = 0; t < 8; t++) {
        const int e = (int)blockIdx.x * 64 + warp * 8 + t;
        if (e >= E) break;

        int uu, vv;
        if (flag64) {
            uu = (int)((const long long*)u_)[e];
            vv = (int)((const long long*)v_)[e];
        } else {
            uu = ((const int*)u_)[e];
            vv = ((const int*)v_)[e];
        }
        const float* zu = z + (size_t)uu * DDIM;
        const float* zv = z + (size_t)vv * DDIM;

        float g0 = 0.f, g1 = 0.f, g2 = 0.f, g3 = 0.f;
        #pragma unroll
        for (int kk = 0; kk < 4; kk++) {
            const int k = lane + kk * 32;
            const float a = zu[k];
            const float b = zv[k];
            const float d = fabsf(a - b);
            const float m = a * b;
            const float4 wA = gw4[k];
            const float4 wB = gw4[128 + k];
            const float4 wD = gw4[256 + k];
            const float4 wM = gw4[384 + k];
            g0 += a * wA.x + b * wB.x + d * wD.x + m * wM.x;
            g1 += a * wA.y + b * wB.y + d * wD.y + m * wM.y;
            g2 += a * wA.z + b * wB.z + d * wD.z + m * wM.z;
            g3 += a * wA.w + b * wB.w + d * wD.w + m * wM.w;
        }
        #pragma unroll
        for (int off = 16; off; off >>= 1) {
            g0 += __shfl_xor_sync(0xffffffffu, g0, off);
            g1 += __shfl_xor_sync(0xffffffffu, g1, off);
            g2 += __shfl_xor_sync(0xffffffffu, g2, off);
            g3 += __shfl_xor_sync(0xffffffffu, g3, off);
        }

        if (lane == 0) {
            float l[NEXP];
            l[0] = g0 + gate_b[0]; l[1] = g1 + gate_b[1];
            l[2] = g2 + gate_b[2]; l[3] = g3 + gate_b[3];
            float mx = l[0];
            #pragma unroll
            for (int j = 1; j < NEXP; j++) mx = fmaxf(mx, l[j]);
            float ex[NEXP]; float s = 0.f;
            #pragma unroll
            for (int j = 0; j < NEXP; j++) { ex[j] = expf(l[j] - mx); s += ex[j]; }
            const float inv = 1.f / s;
            float pr[NEXP];
            #pragma unroll
            for (int j = 0; j < NEXP; j++) pr[j] = ex[j] * inv;
            int arg = 0; float best = pr[0];
            #pragma unroll
            for (int j = 1; j < NEXP; j++) if (pr[j] > best) { best = pr[j]; arg = j; }

            g_topv[e] = best;
            sarg[warp * 8 + t] = arg;

            p0 += pr[0]; p1 += pr[1]; p2 += pr[2]; p3 += pr[3];
        }
    }

    if (lane == 0) {
        wpart[warp][0] = p0; wpart[warp][1] = p1;
        wpart[warp][2] = p2; wpart[warp][3] = p3;
    }
    __syncthreads();

    // block-local ranks -> 4 global atomics per block
    const int e0 = (int)blockIdx.x * 64 + tid;
    if (tid < 64 && e0 < E) {
        srank[tid] = atomicAdd(&scnt[sarg[tid]], 1);
    }
    __syncthreads();
    if (tid < NEXP) {
        sbase[tid] = atomicAdd(&g_counts[tid], scnt[tid]);
        float s = 0.f;
        #pragma unroll
        for (int w = 0; w < 8; w++) s += wpart[w][tid];
        g_partial[blockIdx.x][tid] = s;
    }
    __syncthreads();
    if (tid < 64 && e0 < E) {
        const int a = sarg[tid];
        g_bucket[a][sbase[a] + srank[tid]] = e0;
    }
}

// ---------------- kernel 2: merged expert MLPs (1xTF32, KC=32) ----------------
// One kernel processes every 64-edge tile of every expert.
// MODE (== expert): 0 cat K=256 | 1 dist K=128 | 2 mul K=128 | 3 all K=512
// Scalar fragment loads (conflict-free: banks 8*lq+lg), pre-rounded W,
// X stored by (edge=tid&63, dimgroup=tid>>6) -> conflict-free STS rows.

#define KC      32
#define XSTR    72
#define WSTR    264
#define BUFSZ   (KC * XSTR + KC * WSTR)   // 2304 + 8448 = 10752 floats

__global__ __launch_bounds__(256, 2) void k_experts(
    const float* __restrict__ z,
    const void*  __restrict__ u_, const void* __restrict__ v_,
    const float* __restrict__ cb1, const float* __restrict__ cw2, const float* __restrict__ cb2,
    const float* __restrict__ db1, const float* __restrict__ dw2, const float* __restrict__ db2,
    const float* __restrict__ mb1, const float* __restrict__ mw2, const float* __restrict__ mb2,
    const float* __restrict__ ab1, const float* __restrict__ aw2, const float* __restrict__ ab2,
    float* __restrict__ out)
{
    extern __shared__ __align__(16) float sm[];
    float* sb1 = sm + 2 * BUFSZ;        // [256]
    float* sw2 = sb1 + 256;             // [256]
    float* red = sw2 + 256;             // [64][8]
    float* stv = red + 512;             // [64]
    int*   se  = (int*)(stv + 64);      // [64]
    int*   su  = se + 64;               // [64]
    int*   sv  = su + 64;               // [64]

    const int tid  = threadIdx.x;
    const int warp = tid >> 5;
    const int lane = tid & 31;
    const int lq   = lane & 3;
    const int lg   = lane >> 2;
    const int xe   = tid & 63;          // edge handled by this thread for X fill
    const int xg   = tid >> 6;          // dim-group (8 dims) within chunk

    const int flag64 = g_flag64;

    // W cp.async mapping: 8 x 16B per thread per 32-row chunk
    int wr[8], wc[8];
    #pragma unroll
    for (int i = 0; i < 8; i++) {
        const int idx = tid + i * 256;
        wr[i] = idx >> 6;
        wc[i] = (idx & 63) << 2;
    }

    // tile list over all experts
    const int c0n = g_counts[0], c1n = g_counts[1], c2n = g_counts[2], c3n = g_counts[3];
    const int nt0 = (c0n + 63) >> 6, nt1 = (c1n + 63) >> 6;
    const int nt2 = (c2n + 63) >> 6, nt3 = (c3n + 63) >> 6;
    const int p1 = nt0, p2 = p1 + nt1, p3 = p2 + nt2, total = p3 + nt3;

    for (int t = blockIdx.x; t < total; t += gridDim.x) {
        int ex, tile, K, cnt;
        const float *w1, *b1p, *w2p, *b2p;
        if (t < p1)      { ex = 0; tile = t;      K = 256; cnt = c0n; w1 = g_w1p + OFF_CAT;  b1p = cb1; w2p = cw2; b2p = cb2; }
        else if (t < p2) { ex = 1; tile = t - p1; K = 128; cnt = c1n; w1 = g_w1p + OFF_DIST; b1p = db1; w2p = dw2; b2p = db2; }
        else if (t < p3) { ex = 2; tile = t - p2; K = 128; cnt = c2n; w1 = g_w1p + OFF_MUL;  b1p = mb1; w2p = mw2; b2p = mb2; }
        else             { ex = 3; tile = t - p3; K = 512; cnt = c3n; w1 = g_w1p + OFF_ALL;  b1p = ab1; w2p = aw2; b2p = ab2; }
        const int NCH  = K >> 5;
        const int MODE = ex;

        __syncthreads();   // smem reuse guard across tiles
        if (tid < 256) { sb1[tid] = b1p[tid]; sw2[tid] = w2p[tid]; }
        const float b2s = b2p[0];

        const int base = tile * 64;
        const int nE   = min(64, cnt - base);

        if (tid < 64) {
            int e = (tid < nE) ? g_bucket[ex][base + tid] : -1;
            se[tid]  = e;
            stv[tid] = (e >= 0) ? g_topv[e] : 0.f;
            int uu = 0, vv = 0;
            if (e >= 0) {
                if (flag64) {
                    uu = (int)((const long long*)u_)[e];
                    vv = (int)((const long long*)v_)[e];
                } else {
                    uu = ((const int*)u_)[e];
                    vv = ((const int*)v_)[e];
                }
            }
            su[tid] = uu; sv[tid] = vv;
        }
        __syncthreads();

        const float* zu = z + (size_t)su[xe] * DDIM;
        const float* zv = z + (size_t)sv[xe] * DDIM;

        float acc[4][4][4];
        #pragma unroll
        for (int m = 0; m < 4; m++)
            #pragma unroll
            for (int n = 0; n < 4; n++)
                #pragma unroll
                for (int q = 0; q < 4; q++) acc[m][n][q] = 0.f;

        // ---- prologue: chunk 0 into buffer 0 ----
        {
            float* bW = sm + KC * XSTR;
            #pragma unroll
            for (int i = 0; i < 8; i++) {
                const uint32_t dst = (uint32_t)__cvta_generic_to_shared(bW + wr[i] * WSTR + wc[i]);
                cp_async16(dst, w1 + (size_t)wr[i] * HDIM + wc[i]);
            }
            cp_async_commit();
            const int db = xg * 8;
            const float4 xa0 = *reinterpret_cast<const float4*>(zu + db);
            const float4 xa1 = *reinterpret_cast<const float4*>(zu + db + 4);
            const float4 xb0 = *reinterpret_cast<const float4*>(zv + db);
            const float4 xb1 = *reinterpret_cast<const float4*>(zv + db + 4);
            const float av[8] = { xa0.x, xa0.y, xa0.z, xa0.w, xa1.x, xa1.y, xa1.z, xa1.w };
            const float bv[8] = { xb0.x, xb0.y, xb0.z, xb0.w, xb1.x, xb1.y, xb1.z, xb1.w };
            #pragma unroll
            for (int i = 0; i < 8; i++) {
                float val;
                if (MODE == 0)      val = av[i];
                else if (MODE == 1) val = fabsf(av[i] - bv[i]);
                else if (MODE == 2) val = av[i] * bv[i];
                else                val = av[i];
                sm[(xg * 8 + i) * XSTR + xe] = __uint_as_float(f2tf32(val));
            }
            cp_async_wait0();
        }
        __syncthreads();

        #pragma unroll 1
        for (int cb = 0; cb < NCH; cb++) {
            float* cur = sm + (cb & 1) * BUFSZ;
            float* nxt = sm + ((cb + 1) & 1) * BUFSZ;

            float4 xa0, xa1, xb0, xb1;
            const bool more = (cb + 1 < NCH);
            if (more) {
                const int kb2 = (cb + 1) * KC;
                float* bW = nxt + KC * XSTR;
                #pragma unroll
                for (int i = 0; i < 8; i++) {
                    const uint32_t dst = (uint32_t)__cvta_generic_to_shared(bW + wr[i] * WSTR + wc[i]);
                    cp_async16(dst, w1 + (size_t)(kb2 + wr[i]) * HDIM + wc[i]);
                }
                cp_async_commit();
                const int db = (kb2 & 127) + xg * 8;
                xa0 = *reinterpret_cast<const float4*>(zu + db);
                xa1 = *reinterpret_cast<const float4*>(zu + db + 4);
                xb0 = *reinterpret_cast<const float4*>(zv + db);
                xb1 = *reinterpret_cast<const float4*>(zv + db + 4);
            }

            const float* cX = cur;
            const float* cW = cur + KC * XSTR;

            #pragma unroll
            for (int k8 = 0; k8 < 4; k8++) {
                const int kr   = k8 * 8 + lq;
                const int ncol = warp * 32 + lg;

                uint32_t bh[4][2];
                #pragma unroll
                for (int n = 0; n < 4; n++) {
                    bh[n][0] = __float_as_uint(cW[kr * WSTR + ncol + n * 8]);
                    bh[n][1] = __float_as_uint(cW[(kr + 4) * WSTR + ncol + n * 8]);
                }

                #pragma unroll
                for (int m = 0; m < 4; m++) {
                    const int xi = kr * XSTR + m * 16 + lg;
                    const uint32_t a0 = __float_as_uint(cX[xi]);
                    const uint32_t a1 = __float_as_uint(cX[xi + 8]);
                    const uint32_t a2 = __float_as_uint(cX[xi + 4 * XSTR]);
                    const uint32_t a3 = __float_as_uint(cX[xi + 4 * XSTR + 8]);
                    #pragma unroll
                    for (int n = 0; n < 4; n++)
                        mma_tf32(acc[m][n], a0, a1, a2, a3, bh[n][0], bh[n][1]);
                }
            }

            if (more) {
                const int type = ((cb + 1) * KC) >> 7;
                const float av[8] = { xa0.x, xa0.y, xa0.z, xa0.w, xa1.x, xa1.y, xa1.z, xa1.w };
                const float bv[8] = { xb0.x, xb0.y, xb0.z, xb0.w, xb1.x, xb1.y, xb1.z, xb1.w };
                #pragma unroll
                for (int i = 0; i < 8; i++) {
                    float val;
                    if (MODE == 0)      val = (type == 0) ? av[i] : bv[i];
                    else if (MODE == 1) val = fabsf(av[i] - bv[i]);
                    else if (MODE == 2) val = av[i] * bv[i];
                    else {
                        if (type == 0)      val = av[i];
                        else if (type == 1) val = bv[i];
                        else if (type == 2) val = fabsf(av[i] - bv[i]);
                        else                val = av[i] * bv[i];
                    }
                    nxt[(xg * 8 + i) * XSTR + xe] = __uint_as_float(f2tf32(val));
                }
            }
            cp_async_wait0();
            __syncthreads();
        }

        // ---- epilogue: relu + layer-2 dot, reduce ----
        float ep[4][2];
        #pragma unroll
        for (int m = 0; m < 4; m++) { ep[m][0] = 0.f; ep[m][1] = 0.f; }

        #pragma unroll
        for (int n = 0; n < 4; n++) {
            const int c0 = warp * 32 + n * 8 + 2 * lq;
            const float bb0 = sb1[c0],     bb1 = sb1[c0 + 1];
            const float ww0 = sw2[c0],     ww1 = sw2[c0 + 1];
            #pragma unroll
            for (int m = 0; m < 4; m++) {
                ep[m][0] += fmaxf(acc[m][n][0] + bb0, 0.f) * ww0
                          + fmaxf(acc[m][n][1] + bb1, 0.f) * ww1;
                ep[m][1] += fmaxf(acc[m][n][2] + bb0, 0.f) * ww0
                          + fmaxf(acc[m][n][3] + bb1, 0.f) * ww1;
            }
        }
        #pragma unroll
        for (int m = 0; m < 4; m++) {
            #pragma unroll
            for (int off = 1; off <= 2; off <<= 1) {
                ep[m][0] += __shfl_xor_sync(0xffffffffu, ep[m][0], off);
                ep[m][1] += __shfl_xor_sync(0xffffffffu, ep[m][1], off);
            }
        }
        if (lq == 0) {
            #pragma unroll
            for (int m = 0; m < 4; m++) {
                red[(m * 16 + lg) * 8 + warp]     = ep[m][0];
                red[(m * 16 + lg + 8) * 8 + warp] = ep[m][1];
            }
        }
        __syncthreads();

        if (tid < 64 && se[tid] >= 0) {
            float s = 0.f;
            #pragma unroll
            for (int w = 0; w < 8; w++) s += red[tid * 8 + w];
            out[se[tid]] = stv[tid] * (s + b2s);
        }
    }
}

// ---------------- kernel 6: aux loss reduction (deterministic) ----------------
__global__ __launch_bounds__(256) void k_aux(float* out, int out_size, int nblocks, int E)
{
    __shared__ float s[256];
    float acc[NEXP] = {0.f, 0.f, 0.f, 0.f};
    for (int i = threadIdx.x; i < nblocks; i += 256) {
        #pragma unroll
        for (int j = 0; j < NEXP; j++) acc[j] += g_partial[i][j];
    }
    float tot[NEXP];
    #pragma unroll
    for (int j = 0; j < NEXP; j++) {
        s[threadIdx.x] = acc[j];
        __syncthreads();
        for (int st = 128; st; st >>= 1) {
            if (threadIdx.x < st) s[threadIdx.x] += s[threadIdx.x + st];
            __syncthreads();
        }
        tot[j] = s[0];
        __syncthreads();
    }
    if (threadIdx.x == 0 && out_size > E) {
        float aux = 0.f;
        const float invE = 1.f / (float)E;
        #pragma unroll
        for (int j = 0; j < NEXP; j++) {
            const float m = tot[j] * invE;
            aux += m * m;
        }
        out[E] = aux * (float)NEXP;
    }
}

// ---------------- host launcher ----------------
#define EXP_SMEM ((2 * BUFSZ + 256 + 256 + 512 + 64 + 192) * 4)

extern "C" void kernel_launch(void* const* d_in, const int* in_sizes, int n_in,
                              void* d_out, int out_size)
{
    const float* z       = (const float*)d_in[0];
    const void*  u       = d_in[1];
    const void*  v       = d_in[2];
    const float* gate_w  = (const float*)d_in[3];
    const float* gate_b  = (const float*)d_in[4];
    const float* cat_w1  = (const float*)d_in[5];
    const float* cat_b1  = (const float*)d_in[6];
    const float* cat_w2  = (const float*)d_in[7];
    const float* cat_b2  = (const float*)d_in[8];
    const float* dist_w1 = (const float*)d_in[9];
    const float* dist_b1 = (const float*)d_in[10];
    const float* dist_w2 = (const float*)d_in[11];
    const float* dist_b2 = (const float*)d_in[12];
    const float* mul_w1  = (const float*)d_in[13];
    const float* mul_b1  = (const float*)d_in[14];
    const float* mul_w2  = (const float*)d_in[15];
    const float* mul_b2  = (const float*)d_in[16];
    const float* all_w1  = (const float*)d_in[17];
    const float* all_b1  = (const float*)d_in[18];
    const float* all_w2  = (const float*)d_in[19];
    const float* all_b2  = (const float*)d_in[20];
    float* out = (float*)d_out;

    const int E = in_sizes[1];                 // 262144
    const int gateBlocks = (E + 63) / 64;      // 4096

    cudaFuncSetAttribute(k_experts, cudaFuncAttributeMaxDynamicSharedMemorySize, EXP_SMEM);

    k_init<<<1, 256>>>(u);
    k_prep<<<1024, 256>>>(cat_w1, dist_w1, mul_w1, all_w1);
    k_gate<<<gateBlocks, 256>>>(z, u, v, gate_w, gate_b, E);

    k_experts<<<2048, 256, EXP_SMEM>>>(z, u, v,
        cat_b1, cat_w2, cat_b2,
        dist_b1, dist_w2, dist_b2,
        mul_b1, mul_w2, mul_b2,
        all_b1, all_w2, all_b2,
        out);

    k_aux<<<1, 256>>>(out, out_size, gateBlocks, E);
}